// round 17
// baseline (speedup 1.0000x reference)
#include <cuda_runtime.h>
#include <cuda_fp16.h>
#include <math.h>

#define NN 50000
#define EE 600000
#define DD 128
#define ELLS 96                    // ELL row stride (max supported degree)

// ---------------- scratch (device globals; no allocation allowed) ----------
__device__ float g_deg[NN];
__device__ float g_dinv[NN];
__device__ int   g_cnt[NN];          // per-dst fill cursor / final count
__device__ uint2 g_cell[NN * ELLS];  // ELL slot: (src index, weight bits)
__device__ unsigned g_h16[NN * 64];  // raw messages h as half2 pairs
__device__ unsigned g_a16[NN * 64];  // act(BN0(agg)) as half2 pairs (layer-1 input)

// ---------------- prep kernels ----------------------------------------------
__global__ void k_zero() {
    int i = blockIdx.x * blockDim.x + threadIdx.x;
    if (i < NN) {
        g_cnt[i] = 0;
        g_deg[i] = 0.f;
    }
}

// single edge pass: weighted degree + ELL fill (raw weight); ILP2
__global__ void k_degfill(const int* __restrict__ src, const int* __restrict__ dst,
                          const float* __restrict__ ew) {
    int t = blockIdx.x * blockDim.x + threadIdx.x;
    int stride = gridDim.x * blockDim.x;
    int   dd[2], ss[2];
    float ww[2];
    bool  vv[2];
#pragma unroll
    for (int i = 0; i < 2; i++) {
        int e = t + i * stride;
        vv[i] = (e < EE);
        if (vv[i]) {
            dd[i] = dst[e];
            ss[i] = src[e];
            ww[i] = ew[e];
        }
    }
#pragma unroll
    for (int i = 0; i < 2; i++) {
        if (vv[i]) {
            atomicAdd(&g_deg[dd[i]], ww[i]);
            int c = atomicAdd(&g_cnt[dd[i]], 1);
            if (c < ELLS)
                g_cell[dd[i] * ELLS + c] = make_uint2((unsigned)ss[i],
                                                      __float_as_uint(ww[i]));
        }
    }
}

// fused: dinv compute + store, and in-place slot normalization
__global__ void k_wnormF() {
    int t = blockIdx.x * blockDim.x + threadIdx.x;
    int node = t >> 5;
    int lane = t & 31;
    if (node >= NN) return;
    float dn = rsqrtf(g_deg[node] + 1.0f);   // +1 = self-loop weight
    if (lane == 0) g_dinv[node] = dn;
    int cnt = g_cnt[node];
    if (cnt > ELLS) cnt = ELLS;
    int beg = node * ELLS;
    for (int j = lane; j < cnt; j += 32) {
        uint2 cell = g_cell[beg + j];
        float w = __uint_as_float(cell.y) * dn *
                  rsqrtf(__ldg(&g_deg[cell.x]) + 1.0f);
        g_cell[beg + j].y = __float_as_uint(w);
    }
}

// ---------------- fp16 tensor-core GEMM (ldmatrix mainloop) -----------------
// H16 = A @ W with fp16 inputs, fp32 accumulate (mma.m16n8k16).
// PACKED=0: A is f32 [n][128]. PACKED=1: A is half2-packed [n][64 words].
// SMEM (32-bit words): As[64][68], Ws[128][68] natural [k][n] layout.
#define SMSW 68                                    // smem row stride (words)
#define GEMM_SMEM ((64 * SMSW + 128 * SMSW) * 4)   // 52.2 KB -> 4 blocks/SM

template <int PACKED>
__global__ __launch_bounds__(256, 4) void k_gemm(const void* __restrict__ Ain,
                                                 const float* __restrict__ W,
                                                 unsigned* __restrict__ H16, int n) {
    extern __shared__ unsigned sm[];
    unsigned* As = sm;               // [64][SMSW]  A rows (k halves packed)
    unsigned* Ws = sm + 64 * SMSW;   // [128][SMSW] W natural: row k, n halves

    int tid = threadIdx.x;
    int row0 = blockIdx.x * 64;

    // ---- stage W natural [k][n] as half (coalesced loads, no-conflict stores)
    const float4* W4 = (const float4*)W;
#pragma unroll
    for (int i = 0; i < 16; i++) {
        int idx = tid + i * 256;        // 4096 float4 = 128 k-rows x 32
        int r = idx >> 5, c = idx & 31;
        float4 v = W4[idx];
        __half2 h01 = __floats2half2_rn(v.x, v.y);
        __half2 h23 = __floats2half2_rn(v.z, v.w);
        uint2 pack = make_uint2(*(unsigned*)&h01, *(unsigned*)&h23);
        *(uint2*)&Ws[r * SMSW + 2 * c] = pack;
    }

    // ---- stage A tile as half ----
    if (PACKED) {
        const uint2* A2 = (const uint2*)Ain;    // [row][32] uint2
#pragma unroll
        for (int i = 0; i < 8; i++) {
            int idx = tid + i * 256;
            int r = idx >> 5, c = idx & 31;
            uint2 val = make_uint2(0u, 0u);
            if (row0 + r < n) val = A2[(size_t)(row0 + r) * 32 + c];
            *(uint2*)&As[r * SMSW + 2 * c] = val;
        }
    } else {
        const float4* A4 = (const float4*)Ain;
#pragma unroll
        for (int i = 0; i < 8; i++) {
            int idx = tid + i * 256;        // 2048 float4 = 64 rows x 32
            int r = idx >> 5, c = idx & 31;
            float4 v = make_float4(0.f, 0.f, 0.f, 0.f);
            if (row0 + r < n) v = A4[(size_t)(row0 + r) * 32 + c];
            __half2 h01 = __floats2half2_rn(v.x, v.y);
            __half2 h23 = __floats2half2_rn(v.z, v.w);
            uint2 pack = make_uint2(*(unsigned*)&h01, *(unsigned*)&h23);
            *(uint2*)&As[r * SMSW + 2 * c] = pack;
        }
    }
    __syncthreads();

    int wid = tid >> 5;
    int lane = tid & 31;
    int rw = (wid & 3) * 16;       // row band within tile
    int cwb = (wid >> 2) * 64;     // col half

    // A x4 (non-trans)
    int arow = rw + (lane & 7) + ((lane >> 3) & 1) * 8;
    unsigned aBase = (unsigned)__cvta_generic_to_shared(As + arow * SMSW)
                   + ((lane >> 4) & 1) * 16;

    // B x4 TRANS per n-group g (16 n-cols)
    unsigned bBase[4];
#pragma unroll
    for (int g = 0; g < 4; g++) {
        int krow = (lane & 7) + ((lane >> 3) & 1) * 8;
        int ncol = cwb + g * 16 + ((lane >> 4) & 1) * 8;
        bBase[g] = (unsigned)__cvta_generic_to_shared(Ws + krow * SMSW)
                 + ncol * 2;
    }

    float acc[8][4];
#pragma unroll
    for (int nt = 0; nt < 8; nt++)
#pragma unroll
        for (int j = 0; j < 4; j++) acc[nt][j] = 0.f;

#pragma unroll
    for (int kt = 0; kt < 8; kt++) {
        unsigned a0, a1, a2, a3;
        asm volatile("ldmatrix.sync.aligned.m8n8.x4.shared.b16 {%0,%1,%2,%3}, [%4];"
                     : "=r"(a0), "=r"(a1), "=r"(a2), "=r"(a3)
                     : "r"(aBase + kt * 32));
        unsigned kOff = kt * 16 * SMSW * 4;   // advance 16 k-rows
#pragma unroll
        for (int g = 0; g < 4; g++) {
            unsigned b0, b1, b2, b3;
            asm volatile("ldmatrix.sync.aligned.m8n8.x4.trans.shared.b16 {%0,%1,%2,%3}, [%4];"
                         : "=r"(b0), "=r"(b1), "=r"(b2), "=r"(b3)
                         : "r"(bBase[g] + kOff));
            asm("mma.sync.aligned.m16n8k16.row.col.f32.f16.f16.f32 "
                "{%0,%1,%2,%3}, {%4,%5,%6,%7}, {%8,%9}, {%0,%1,%2,%3};"
                : "+f"(acc[2 * g][0]), "+f"(acc[2 * g][1]),
                  "+f"(acc[2 * g][2]), "+f"(acc[2 * g][3])
                : "r"(a0), "r"(a1), "r"(a2), "r"(a3), "r"(b0), "r"(b1));
            asm("mma.sync.aligned.m16n8k16.row.col.f32.f16.f16.f32 "
                "{%0,%1,%2,%3}, {%4,%5,%6,%7}, {%8,%9}, {%0,%1,%2,%3};"
                : "+f"(acc[2 * g + 1][0]), "+f"(acc[2 * g + 1][1]),
                  "+f"(acc[2 * g + 1][2]), "+f"(acc[2 * g + 1][3])
                : "r"(a0), "r"(a1), "r"(a2), "r"(a3), "r"(b2), "r"(b3));
        }
    }

    // ---- epilogue: store raw fp16 message pairs ----
    int q = lane >> 2;             // 0..7
    int m = lane & 3;              // 0..3
    int r_lo = row0 + rw + q;      // rows r_lo and r_lo+8
#pragma unroll
    for (int nt = 0; nt < 8; nt++) {
        int col = cwb + nt * 8 + 2 * m;
        if (r_lo < n) {
            __half2 hv = __floats2half2_rn(acc[nt][0], acc[nt][1]);
            H16[(size_t)r_lo * 64 + (col >> 1)] = *(unsigned*)&hv;
        }
        if (r_lo + 8 < n) {
            __half2 hv = __floats2half2_rn(acc[nt][2], acc[nt][3]);
            H16[(size_t)(r_lo + 8) * 64 + (col >> 1)] = *(unsigned*)&hv;
        }
    }
}

// ---------------- gather: one warp per destination node --------------------
// acc = dinv^2 * m[node] + sum_j w_j * m[src_j]   (w fully normalized in cell)
// MODE 0: apply BN0 + adaptive act, output half2 pairs (layer-1 input).
// MODE 1: apply BN1, output f32 (final result).
// Folded BN params computed per-block into smem (b, ga, be, mu, va are tiny
// L1-resident arrays; 128 threads x 5 loads per block).
template <int MODE>
__global__ __launch_bounds__(256) void k_gather(const uint2* __restrict__ h,
                                                void* __restrict__ outv,
                                                const float* __restrict__ bb,
                                                const float* __restrict__ ga,
                                                const float* __restrict__ be,
                                                const float* __restrict__ mu,
                                                const float* __restrict__ va,
                                                const float* __restrict__ act) {
    __shared__ float s_sc[DD], s_sh[DD], s_alpha;
    int tid = threadIdx.x;
    if (tid < DD) {
        float sc = ga[tid] * rsqrtf(va[tid] + 1e-5f);
        s_sc[tid] = sc;
        s_sh[tid] = be[tid] + (bb[tid] - mu[tid]) * sc;
    }
    if (MODE == 0 && tid == 0) s_alpha = 1.0f / (1.0f + expf(-act[0]));
    __syncthreads();

    int t = blockIdx.x * blockDim.x + tid;
    int node = t >> 5;
    int lane = t & 31;
    if (node >= NN) return;

    int beg = node * ELLS;
    int cnt = g_cnt[node];
    if (cnt > ELLS) cnt = ELLS;
    int end = beg + cnt;

    float d = g_dinv[node];
    d *= d;
    uint2 sr = h[(size_t)node * 32 + lane];
    float2 slo = __half22float2(*(__half2*)&sr.x);
    float2 shi = __half22float2(*(__half2*)&sr.y);
    float4 acc = make_float4(slo.x * d, slo.y * d, shi.x * d, shi.y * d);

    int j = beg;
    for (; j + 3 < end; j += 4) {
        uint2 e0 = __ldg(&g_cell[j]);
        uint2 e1 = __ldg(&g_cell[j + 1]);
        uint2 e2 = __ldg(&g_cell[j + 2]);
        uint2 e3 = __ldg(&g_cell[j + 3]);
        float w0 = __uint_as_float(e0.y);
        float w1 = __uint_as_float(e1.y);
        float w2 = __uint_as_float(e2.y);
        float w3 = __uint_as_float(e3.y);
        uint2 r0 = h[(size_t)e0.x * 32 + lane];
        uint2 r1 = h[(size_t)e1.x * 32 + lane];
        uint2 r2 = h[(size_t)e2.x * 32 + lane];
        uint2 r3 = h[(size_t)e3.x * 32 + lane];
        float2 l0 = __half22float2(*(__half2*)&r0.x), h0 = __half22float2(*(__half2*)&r0.y);
        float2 l1 = __half22float2(*(__half2*)&r1.x), h1 = __half22float2(*(__half2*)&r1.y);
        float2 l2 = __half22float2(*(__half2*)&r2.x), h2 = __half22float2(*(__half2*)&r2.y);
        float2 l3 = __half22float2(*(__half2*)&r3.x), h3 = __half22float2(*(__half2*)&r3.y);
        acc.x += w0 * l0.x + w1 * l1.x + w2 * l2.x + w3 * l3.x;
        acc.y += w0 * l0.y + w1 * l1.y + w2 * l2.y + w3 * l3.y;
        acc.z += w0 * h0.x + w1 * h1.x + w2 * h2.x + w3 * h3.x;
        acc.w += w0 * h0.y + w1 * h1.y + w2 * h2.y + w3 * h3.y;
    }
    for (; j < end; j++) {
        uint2 e = __ldg(&g_cell[j]);
        float w = __uint_as_float(e.y);
        uint2 r = h[(size_t)e.x * 32 + lane];
        float2 lo = __half22float2(*(__half2*)&r.x);
        float2 hi = __half22float2(*(__half2*)&r.y);
        acc.x += w * lo.x;
        acc.y += w * lo.y;
        acc.z += w * hi.x;
        acc.w += w * hi.y;
    }

    int c0 = lane * 4;
    float r[4] = {acc.x, acc.y, acc.z, acc.w};
#pragma unroll
    for (int jj = 0; jj < 4; jj++)
        r[jj] = r[jj] * s_sc[c0 + jj] + s_sh[c0 + jj];

    if (MODE == 0) {
        float alpha = s_alpha;
#pragma unroll
        for (int jj = 0; jj < 4; jj++) {
            float v = r[jj];
            float relu = fmaxf(v, 0.f);
            float gelu = 0.5f * v * (1.f + erff(v * 0.70710678118654752f));
            r[jj] = alpha * relu + (1.f - alpha) * gelu;
        }
        __half2 h01 = __floats2half2_rn(r[0], r[1]);
        __half2 h23 = __floats2half2_rn(r[2], r[3]);
        uint2 pack = make_uint2(*(unsigned*)&h01, *(unsigned*)&h23);
        ((uint2*)outv)[(size_t)node * 32 + lane] = pack;
    } else {
        ((float4*)outv)[(size_t)node * 32 + lane] = make_float4(r[0], r[1], r[2], r[3]);
    }
}

// ---------------- launch ----------------------------------------------------
extern "C" void kernel_launch(void* const* d_in, const int* in_sizes, int n_in,
                              void* d_out, int out_size) {
    const float* x  = (const float*)d_in[0];
    const int*   ei = (const int*)d_in[1];     // [2,E]: row0=src, row1=dst
    const float* ew = (const float*)d_in[2];
    const float* W0 = (const float*)d_in[3];
    const float* b0 = (const float*)d_in[4];
    const float* W1 = (const float*)d_in[5];
    const float* b1 = (const float*)d_in[6];
    const float* ga0 = (const float*)d_in[7];
    const float* be0 = (const float*)d_in[8];
    const float* m0  = (const float*)d_in[9];
    const float* v0  = (const float*)d_in[10];
    const float* ga1 = (const float*)d_in[11];
    const float* be1 = (const float*)d_in[12];
    const float* m1  = (const float*)d_in[13];
    const float* v1  = (const float*)d_in[14];
    const float* act = (const float*)d_in[15];
    float* out = (float*)d_out;

    const int* src = ei;
    const int* dst = ei + EE;

    unsigned* hD; cudaGetSymbolAddress((void**)&hD, g_h16);
    unsigned* aD; cudaGetSymbolAddress((void**)&aD, g_a16);

    cudaFuncSetAttribute(k_gemm<0>, cudaFuncAttributeMaxDynamicSharedMemorySize, GEMM_SMEM);
    cudaFuncSetAttribute(k_gemm<1>, cudaFuncAttributeMaxDynamicSharedMemorySize, GEMM_SMEM);

    // side stream + fork/join events (created once; capture-safe fork pattern)
    static cudaStream_t sA = nullptr;
    static cudaEvent_t evFork = nullptr, evJoin = nullptr;
    if (sA == nullptr) {
        cudaStreamCreateWithFlags(&sA, cudaStreamNonBlocking);
        cudaEventCreateWithFlags(&evFork, cudaEventDisableTiming);
        cudaEventCreateWithFlags(&evJoin, cudaEventDisableTiming);
    }

    const int B = 256;
    int gN    = (NN + B - 1) / B;
    int gE2   = (EE + 2 * B - 1) / (2 * B);
    int gGth  = (NN * 32 + B - 1) / B;
    int gGemm = (NN + 63) / 64;

    // ---- main stream: zero first (both streams depend on it) ----
    k_zero<<<gN, B>>>();

    // ---- fork: graph prep on side stream, concurrent with layer-0 GEMM ----
    cudaEventRecord(evFork, 0);
    cudaStreamWaitEvent(sA, evFork, 0);
    k_degfill<<<gE2, B, 0, sA>>>(src, dst, ew);
    k_wnormF<<<gGth, B, 0, sA>>>();
    cudaEventRecord(evJoin, sA);

    // ---- main stream: layer-0 GEMM (graph-independent) ----
    k_gemm<0><<<gGemm, B, GEMM_SMEM>>>(x, W0, hD, NN);

    // ---- join: gather needs ELL + dinv ----
    cudaStreamWaitEvent(0, evJoin, 0);
    // gather0: aggregate + BN0 + adaptive act -> fp16 layer-1 input
    k_gather<0><<<gGth, B>>>((const uint2*)hD, aD, b0, ga0, be0, m0, v0, act);

    // layer 1: gemm on packed fp16 input; gather1 applies BN1 -> f32 out
    k_gemm<1><<<gGemm, B, GEMM_SMEM>>>(aD, W1, hD, NN);
    k_gather<1><<<gGth, B>>>((const uint2*)hD, out, b1, ga1, be1, m1, v1, nullptr);
}